// round 9
// baseline (speedup 1.0000x reference)
#include <cuda_runtime.h>
#include <math.h>

#define NPERROW (512*512)            // 262144
#define NROWS   128
#define NV4     (NPERROW/4)          // 65536
#define FULLM   0xFFFFFFFFu

// ---- gather / gate shape ----
#define CHUNKS  16
#define GTH     256
#define V4C     (NV4/CHUNKS)         // 4096 float4 per chunk
#define V4T     (V4C/GTH)            // 16 float4 per thread
#define GWARPS  (GTH/32)             // 8
#define TCAP    24                   // per-thread stage cap (exp 2.9, ~11 sigma)
#define CSEG    1024                 // per-chunk global segment cap (exp ~746)
#define MCAP    (CHUNKS*CSEG)        // 16384

// ---- selection (3-pass radix: 11 + 11 + 10 bits) ----
#define SELBINS 2048

__device__ unsigned int g_buf[NROWS][MCAP];    // 8 MB scratch
__device__ unsigned int g_ccnt[NROWS][CHUNKS]; // per-chunk counts (0xFFFFFFFF = overflow)
__device__ int          g_done[NROWS];         // zero-init; self-resetting
__device__ float g_scale[NROWS];
__device__ float g_t[NROWS];

// monotone float -> uint key
__device__ __forceinline__ unsigned int f2k(float f) {
    unsigned int u = __float_as_uint(f);
    return u ^ ((unsigned int)((int)u >> 31) | 0x80000000u);
}
__device__ __forceinline__ float k2f(unsigned int k) {
    unsigned int u = (k & 0x80000000u) ? (k ^ 0x80000000u) : ~k;
    return __uint_as_float(u);
}
__device__ __forceinline__ float ex2a(float x){ float r; asm("ex2.approx.ftz.f32 %0, %1;" : "=f"(r) : "f"(x)); return r; }
__device__ __forceinline__ float rcpa(float x){ float r; asm("rcp.approx.ftz.f32 %0, %1;" : "=f"(r) : "f"(x)); return r; }

// per-key histogram insert for pass 1/2/3 (sel0..3 cached in registers)
__device__ __forceinline__ void hist_insert(int pass, unsigned int k, unsigned int* arena,
                                            unsigned int sel0, unsigned int sel1,
                                            unsigned int sel2, unsigned int sel3)
{
    if (pass == 1) {
        atomicAdd(&arena[k >> 21], 1u);
    } else if (pass == 2) {
        unsigned int hi = k >> 21, b = (k >> 10) & 2047u;
        if (hi == sel0) atomicAdd(&arena[0 * SELBINS + b], 1u);
        if (hi == sel1) atomicAdd(&arena[1 * SELBINS + b], 1u);
        if (hi == sel2) atomicAdd(&arena[2 * SELBINS + b], 1u);
        if (hi == sel3) atomicAdd(&arena[3 * SELBINS + b], 1u);
    } else {
        unsigned int hi = k >> 10, b = k & 1023u;
        if (hi == sel0) atomicAdd(&arena[0 * SELBINS + b], 1u);
        if (hi == sel1) atomicAdd(&arena[1 * SELBINS + b], 1u);
        if (hi == sel2) atomicAdd(&arena[2 * SELBINS + b], 1u);
        if (hi == sel3) atomicAdd(&arena[3 * SELBINS + b], 1u);
    }
}

// ===================== Kernel A: gather + last-CTA-per-row selection =====================
__global__ __launch_bounds__(GTH, 6)
void gather_select_kernel(const float* __restrict__ x,
                          const float* __restrict__ alpha_p,
                          const float* __restrict__ beta_p)
{
    __shared__ unsigned int arena[4 * SELBINS];   // 32 KB: gather stage, then radix hists
    __shared__ unsigned int wsum[GWARPS];
    __shared__ int s_ov, s_last, s_mode, s_redo;
    __shared__ unsigned int s_cnt[CHUNKS];
    __shared__ unsigned int s_M;
    __shared__ unsigned int s_sel[4], s_lr[4];

    const int tid  = threadIdx.x;
    const int lane = tid & 31;
    const int wid  = tid >> 5;
    const int row  = blockIdx.x >> 4;
    const int chk  = blockIdx.x & (CHUNKS - 1);
    const float4* xr = (const float4*)(x + (size_t)row * NPERROW) + (size_t)chk * V4C;

    if (tid == 0) s_ov = 0;
    __syncthreads();

    // ---------- gather this chunk's |x|>2 keys ----------
    unsigned int* stage = arena;   // TCAP*GTH = 6144 words <= 8192
    unsigned int cnt = 0;
    #pragma unroll
    for (int it = 0; it < V4T / 4; it++) {
        float4 v0 = __ldcs(&xr[tid + (it * 4 + 0) * GTH]);
        float4 v1 = __ldcs(&xr[tid + (it * 4 + 1) * GTH]);
        float4 v2 = __ldcs(&xr[tid + (it * 4 + 2) * GTH]);
        float4 v3 = __ldcs(&xr[tid + (it * 4 + 3) * GTH]);
        float f[16] = {v0.x, v0.y, v0.z, v0.w, v1.x, v1.y, v1.z, v1.w,
                       v2.x, v2.y, v2.z, v2.w, v3.x, v3.y, v3.z, v3.w};
        #pragma unroll
        for (int e = 0; e < 16; e++) {
            if (fabsf(f[e]) > 2.0f) {
                if (cnt < TCAP) stage[cnt * GTH + tid] = f2k(f[e]);
                cnt++;
            }
        }
    }
    if (cnt > TCAP) s_ov = 1;   // benign race; ordered by barriers below

    // block exclusive scan of per-thread counts
    unsigned int inc = cnt;
    #pragma unroll
    for (int o = 1; o < 32; o <<= 1) {
        unsigned int t = __shfl_up_sync(FULLM, inc, o);
        if (lane >= o) inc += t;
    }
    if (lane == 31) wsum[wid] = inc;
    __syncthreads();
    if (tid < GWARPS) {
        unsigned int w = wsum[tid];
        #pragma unroll
        for (int o = 1; o < GWARPS; o <<= 1) {
            unsigned int t = __shfl_up_sync(0xFFu, w, o);
            if (tid >= o) w += t;
        }
        wsum[tid] = w;
    }
    __syncthreads();

    unsigned int pre   = (wid ? wsum[wid - 1] : 0u) + inc - cnt;
    unsigned int total = wsum[GWARPS - 1];
    int ov = s_ov || (total > CSEG);

    if (!ov) {
        unsigned int* dst = &g_buf[row][chk * CSEG + pre];
        for (unsigned int j = 0; j < cnt; j++) dst[j] = stage[j * GTH + tid];
    }
    if (tid == 0) g_ccnt[row][chk] = ov ? 0xFFFFFFFFu : total;

    // ---------- release: publish writes, bump done counter ----------
    __threadfence();
    __syncthreads();
    if (tid == 0) {
        int d = atomicAdd(&g_done[row], 1);
        s_last = (d == CHUNKS - 1);
    }
    __syncthreads();
    if (!s_last) return;

    // ---------- last CTA of this row: selection ----------
    if (tid == 0) g_done[row] = 0;   // reset for next replay
    __threadfence();                 // acquire: other CTAs' g_buf/g_ccnt now visible

    if (tid == 0) {
        unsigned int m = 0; int bad = 0;
        #pragma unroll
        for (int c = 0; c < CHUNKS; c++) {
            unsigned int cc = g_ccnt[row][c];
            if (cc > CSEG) { bad = 1; cc = 0; }
            s_cnt[c] = cc;
            m += cc;
        }
        if (m < 5246u) bad = 1;      // need >=2623 per tail
        s_M = m;
        s_mode = bad ? 1 : 0;
    }
    __syncthreads();

    const float4* xr4 = (const float4*)(x + (size_t)row * NPERROW);
    const unsigned int KNEG2 = f2k(-2.0f);   // 0x3FFFFFFF
    const unsigned int KPOS2 = f2k( 2.0f);   // 0xC0000000

    for (;;) {
        const int mode = s_mode;
        if (tid < 4) {
            unsigned int M = s_M;
            unsigned int R = (mode == 0)
                ? ((tid < 2) ? (2621u + (unsigned int)tid) : (M - 2623u + (unsigned int)(tid - 2)))
                : ((tid < 2) ? (2621u + (unsigned int)tid) : (259521u + (unsigned int)(tid - 2)));
            s_lr[tid] = R;
            s_sel[tid] = 0u;
        }
        __syncthreads();

        for (int pass = 1; pass <= 3; pass++) {
            const int nb = (pass == 1) ? SELBINS : 4 * SELBINS;
            for (int j = tid; j < nb; j += GTH) arena[j] = 0u;
            __syncthreads();

            const unsigned int sel0 = s_sel[0], sel1 = s_sel[1];
            const unsigned int sel2 = s_sel[2], sel3 = s_sel[3];

            if (mode == 0) {
                for (int j0 = tid; j0 < MCAP; j0 += GTH * 4) {
                    unsigned int k[4]; bool val[4];
                    #pragma unroll
                    for (int s = 0; s < 4; s++) {
                        int j = j0 + s * GTH;
                        val[s] = ((unsigned int)(j & (CSEG - 1)) < s_cnt[j >> 10]);
                        k[s] = g_buf[row][j];
                    }
                    #pragma unroll
                    for (int s = 0; s < 4; s++)
                        if (val[s]) hist_insert(pass, k[s], arena, sel0, sel1, sel2, sel3);
                }
            } else {
                // exact full-row fallback domain
                for (int i = tid; i < NV4; i += GTH) {
                    float4 v = xr4[i];
                    hist_insert(pass, f2k(v.x), arena, sel0, sel1, sel2, sel3);
                    hist_insert(pass, f2k(v.y), arena, sel0, sel1, sel2, sel3);
                    hist_insert(pass, f2k(v.z), arena, sel0, sel1, sel2, sel3);
                    hist_insert(pass, f2k(v.w), arena, sel0, sel1, sel2, sel3);
                }
            }
            __syncthreads();

            // locate: warp q handles rank q (pass 1: all read the shared bank 0)
            if (wid < 4) {
                unsigned int* h = arena + ((pass == 1) ? 0 : wid * SELBINS);
                unsigned int lr = s_lr[wid];
                int base = lane * 64;
                unsigned int s = 0;
                #pragma unroll 8
                for (int i = 0; i < 64; i++) s += h[base + i];
                unsigned int inc2 = s;
                #pragma unroll
                for (int o = 1; o < 32; o <<= 1) {
                    unsigned int t = __shfl_up_sync(FULLM, inc2, o);
                    if (lane >= o) inc2 += t;
                }
                unsigned int run = inc2 - s;   // exclusive prefix of this lane's 64 bins
                for (int i = 0; i < 64; i++) {
                    unsigned int cc = h[base + i];
                    if (run <= lr && lr < run + cc) {
                        unsigned int bin = (unsigned int)(base + i);
                        unsigned int ns = (pass == 1) ? bin
                                        : (pass == 2) ? ((s_sel[wid] << 11) | bin)
                                                      : ((s_sel[wid] << 10) | bin);
                        s_sel[wid] = ns;
                        s_lr[wid]  = lr - run;
                    }
                    run += cc;
                }
            }
            __syncthreads();
        }

        if (tid == 0) {
            int redo = 0;
            if (mode == 0) {
                // selected order stats must lie strictly beyond +/-2 for rank mapping to hold
                if (!(s_sel[1] < KNEG2 && s_sel[2] > KPOS2)) { redo = 1; s_mode = 1; }
            }
            s_redo = redo;
        }
        __syncthreads();
        if (!s_redo) break;
    }

    // ---------- threshold ----------
    if (tid == 0) {
        float v[4];
        #pragma unroll
        for (int q = 0; q < 4; q++) v[q] = k2f(s_sel[q]);

        double posLo  = 0.01 * (double)(NPERROW - 1);
        double posHi  = 0.99 * (double)(NPERROW - 1);
        double fracLo = posLo - 2621.0;
        double fracHi = posHi - 259521.0;

        double i1  = (double)v[0] + fracLo * ((double)v[1] - (double)v[0]);
        double i99 = (double)v[2] + fracHi * ((double)v[3] - (double)v[2]);

        float alpha = alpha_p[0];
        float beta  = beta_p[0];
        float th = (float)(i1 + (i99 - i1) * (double)alpha);
        float mask   = (th > 1e-14f) ? 1.0f : 0.0f;
        float th_new = th * mask + (1.0f - mask);
        g_scale[row] = beta / th_new;
        g_t[row]     = th * mask;
    }
}

// ===================== Kernel B: streaming gate =====================
__global__ __launch_bounds__(GTH)
void gate_kernel(const float* __restrict__ x, float* __restrict__ out)
{
    const int c   = blockIdx.x;
    const int row = c >> 4;            // CHUNKS = 16
    const int chk = c & 15;
    const float4* xr   = (const float4*)(x   + (size_t)row * NPERROW) + (size_t)chk * V4C;
    float4*       outr = (float4*)      (out + (size_t)row * NPERROW) + (size_t)chk * V4C;

    const float scale = g_scale[row];
    const float t     = g_t[row];
    const float L2E   = 1.4426950408889634f;
    const float a = scale * L2E;        // exp(-(scale*(|x|-t))) = 2^(-a*|x| + b)
    const float b = scale * t * L2E;

    #pragma unroll 4
    for (int i = threadIdx.x; i < V4C; i += GTH) {
        float4 v = __ldcs(&xr[i]);
        float4 o;
        o.x = fmaxf(v.x, 0.0f) * rcpa(1.0f + ex2a(fmaf(fabsf(v.x), -a, b)));
        o.y = fmaxf(v.y, 0.0f) * rcpa(1.0f + ex2a(fmaf(fabsf(v.y), -a, b)));
        o.z = fmaxf(v.z, 0.0f) * rcpa(1.0f + ex2a(fmaf(fabsf(v.z), -a, b)));
        o.w = fmaxf(v.w, 0.0f) * rcpa(1.0f + ex2a(fmaf(fabsf(v.w), -a, b)));
        __stcs(&outr[i], o);
    }
}

extern "C" void kernel_launch(void* const* d_in, const int* in_sizes, int n_in,
                              void* d_out, int out_size)
{
    const float* x     = (const float*)d_in[0];
    const float* alpha = (const float*)d_in[1];
    const float* beta  = (const float*)d_in[2];
    float* out = (float*)d_out;

    gather_select_kernel<<<NROWS * CHUNKS, GTH>>>(x, alpha, beta);
    gate_kernel<<<NROWS * CHUNKS, GTH>>>(x, out);
}

// round 10
// speedup vs baseline: 1.7276x; 1.7276x over previous
#include <cuda_runtime.h>
#include <math.h>

#define NPERROW (512*512)            // 262144
#define NROWS   128
#define NV4     (NPERROW/4)          // 65536
#define FULLM   0xFFFFFFFFu

// ---- gather / gate shape ----
#define CHUNKS  16
#define GTH     256
#define V4C     (NV4/CHUNKS)         // 4096 float4 per chunk
#define V4T     (V4C/GTH)            // 16 float4 per thread
#define GWARPS  (GTH/32)             // 8
#define TCAP    24                   // per-thread stage cap (exp 2.9, ~11 sigma)
#define CSEG    1024                 // per-chunk global segment cap (exp ~746)
#define MCAP    (CHUNKS*CSEG)        // 16384

// ---- selection (3-pass radix: 11 + 11 + 10 bits) ----
#define STH     1024
#define SELBINS 2048
#define REP     8                    // pass-1 histogram replicas
#define RSTR    2052                 // replica stride (4-word shift -> distinct banks)
#define SEL_SMEM_WORDS (MCAP + REP*RSTR)          // 16384 + 16416 = 32800
#define SEL_SMEM_BYTES (SEL_SMEM_WORDS*4)         // 131200

__device__ unsigned int g_buf[NROWS][MCAP];    // 8 MB scratch
__device__ unsigned int g_ccnt[NROWS][CHUNKS]; // per-chunk counts (0xFFFFFFFF = overflow)
__device__ float g_scale[NROWS];
__device__ float g_t[NROWS];

// monotone float -> uint key
__device__ __forceinline__ unsigned int f2k(float f) {
    unsigned int u = __float_as_uint(f);
    return u ^ ((unsigned int)((int)u >> 31) | 0x80000000u);
}
__device__ __forceinline__ float k2f(unsigned int k) {
    unsigned int u = (k & 0x80000000u) ? (k ^ 0x80000000u) : ~k;
    return __uint_as_float(u);
}
__device__ __forceinline__ float ex2a(float x){ float r; asm("ex2.approx.ftz.f32 %0, %1;" : "=f"(r) : "f"(x)); return r; }
__device__ __forceinline__ float rcpa(float x){ float r; asm("rcp.approx.ftz.f32 %0, %1;" : "=f"(r) : "f"(x)); return r; }

// ===================== Kernel 1: wide tail gather (identical to proven R8) =====================
__global__ __launch_bounds__(GTH)
void gather_kernel(const float* __restrict__ x)
{
    __shared__ unsigned int stage[TCAP * GTH];   // per-thread stripes, conflict-free
    __shared__ unsigned int wsum[GWARPS];
    __shared__ int s_ov;

    const int tid  = threadIdx.x;
    const int lane = tid & 31;
    const int wid  = tid >> 5;
    const int row  = blockIdx.x >> 4;
    const int chk  = blockIdx.x & (CHUNKS - 1);
    const float4* xr = (const float4*)(x + (size_t)row * NPERROW) + (size_t)chk * V4C;

    if (tid == 0) s_ov = 0;
    __syncthreads();

    unsigned int cnt = 0;
    #pragma unroll
    for (int it = 0; it < V4T / 4; it++) {
        float4 v0 = __ldcs(&xr[tid + (it * 4 + 0) * GTH]);
        float4 v1 = __ldcs(&xr[tid + (it * 4 + 1) * GTH]);
        float4 v2 = __ldcs(&xr[tid + (it * 4 + 2) * GTH]);
        float4 v3 = __ldcs(&xr[tid + (it * 4 + 3) * GTH]);
        float f[16] = {v0.x, v0.y, v0.z, v0.w, v1.x, v1.y, v1.z, v1.w,
                       v2.x, v2.y, v2.z, v2.w, v3.x, v3.y, v3.z, v3.w};
        #pragma unroll
        for (int e = 0; e < 16; e++) {
            if (fabsf(f[e]) > 2.0f) {
                if (cnt < TCAP) stage[cnt * GTH + tid] = f2k(f[e]);
                cnt++;
            }
        }
    }
    if (cnt > TCAP) s_ov = 1;

    unsigned int inc = cnt;
    #pragma unroll
    for (int o = 1; o < 32; o <<= 1) {
        unsigned int t = __shfl_up_sync(FULLM, inc, o);
        if (lane >= o) inc += t;
    }
    if (lane == 31) wsum[wid] = inc;
    __syncthreads();
    if (tid < GWARPS) {
        unsigned int w = wsum[tid];
        #pragma unroll
        for (int o = 1; o < GWARPS; o <<= 1) {
            unsigned int t = __shfl_up_sync(0xFFu, w, o);
            if (tid >= o) w += t;
        }
        wsum[tid] = w;
    }
    __syncthreads();

    unsigned int pre   = (wid ? wsum[wid - 1] : 0u) + inc - cnt;
    unsigned int total = wsum[GWARPS - 1];
    int ov = s_ov || (total > CSEG);

    if (!ov) {
        unsigned int* dst = &g_buf[row][chk * CSEG + pre];
        for (unsigned int j = 0; j < cnt; j++) dst[j] = stage[j * GTH + tid];
    }
    if (tid == 0) g_ccnt[row][chk] = ov ? 0xFFFFFFFFu : total;
}

// ===================== Kernel 2: per-row 3-pass radix select =====================
extern __shared__ unsigned int smem_u[];

__device__ __forceinline__ void rs_insert(int pass, unsigned int k, unsigned int* arena,
                                          int rep,
                                          unsigned int sel0, unsigned int sel1,
                                          unsigned int sel2, unsigned int sel3)
{
    if (pass == 1) {
        atomicAdd(&arena[rep * RSTR + (k >> 21)], 1u);
    } else if (pass == 2) {
        unsigned int hi = k >> 21, b = (k >> 10) & 2047u;
        if (hi == sel0) atomicAdd(&arena[0 * SELBINS + b], 1u);
        if (hi == sel1) atomicAdd(&arena[1 * SELBINS + b], 1u);
        if (hi == sel2) atomicAdd(&arena[2 * SELBINS + b], 1u);
        if (hi == sel3) atomicAdd(&arena[3 * SELBINS + b], 1u);
    } else {
        unsigned int hi = k >> 10, b = k & 1023u;
        if (hi == sel0) atomicAdd(&arena[0 * SELBINS + b], 1u);
        if (hi == sel1) atomicAdd(&arena[1 * SELBINS + b], 1u);
        if (hi == sel2) atomicAdd(&arena[2 * SELBINS + b], 1u);
        if (hi == sel3) atomicAdd(&arena[3 * SELBINS + b], 1u);
    }
}

__global__ __launch_bounds__(STH, 1)
void select_kernel(const float* __restrict__ x,
                   const float* __restrict__ alpha_p,
                   const float* __restrict__ beta_p)
{
    unsigned int* mix   = smem_u;          // MCAP
    unsigned int* arena = mix + MCAP;      // REP*RSTR (>= 4*SELBINS for pass 2/3)

    __shared__ unsigned int cpre[CHUNKS + 1];
    __shared__ unsigned int s_M;
    __shared__ int          s_mode, s_redo;
    __shared__ unsigned int s_sel[4], s_lr[4];

    const int tid  = threadIdx.x;
    const int lane = tid & 31;
    const int wid  = tid >> 5;
    const int row  = blockIdx.x;
    const float4* xr = (const float4*)(x + (size_t)row * NPERROW);

    if (tid == 0) {
        unsigned int t = 0; int bad = 0;
        #pragma unroll
        for (int c = 0; c < CHUNKS; c++) {
            unsigned int cc = g_ccnt[row][c];
            if (cc > CSEG) { bad = 1; cc = 0; }
            cpre[c] = t;
            t += cc;
        }
        cpre[CHUNKS] = t;
        if (t < 5246u) bad = 1;   // both tails need >= 2623 elements
        s_M = t;
        s_mode = bad ? 1 : 0;
    }
    __syncthreads();

    const unsigned int M = s_M;
    if (s_mode == 0) {
        #pragma unroll
        for (int c = 0; c < CHUNKS; c++) {
            unsigned int cnt = cpre[c + 1] - cpre[c];   // <= CSEG = 1024 = STH
            if ((unsigned int)tid < cnt) mix[cpre[c] + tid] = g_buf[row][c * CSEG + tid];
        }
    }
    __syncthreads();

    const unsigned int KNEG2 = f2k(-2.0f);   // 0x3FFFFFFF
    const unsigned int KPOS2 = f2k( 2.0f);   // 0xC0000000

    for (;;) {
        const int mode = s_mode;
        if (tid < 4) {
            unsigned int R = (mode == 0)
                ? ((tid < 2) ? (2621u + (unsigned int)tid) : (M - 2623u + (unsigned int)(tid - 2)))
                : ((tid < 2) ? (2621u + (unsigned int)tid) : (259521u + (unsigned int)(tid - 2)));
            s_lr[tid] = R;
            s_sel[tid] = 0u;
        }
        __syncthreads();

        for (int pass = 1; pass <= 3; pass++) {
            const int nz = (pass == 1) ? (REP * RSTR) : (4 * SELBINS);
            for (int j = tid; j < nz; j += STH) arena[j] = 0u;
            __syncthreads();

            const unsigned int sel0 = s_sel[0], sel1 = s_sel[1];
            const unsigned int sel2 = s_sel[2], sel3 = s_sel[3];
            const int rep = wid & (REP - 1);

            if (mode == 0) {
                for (unsigned int i = tid; i < M; i += STH)
                    rs_insert(pass, mix[i], arena, rep, sel0, sel1, sel2, sel3);
            } else {
                for (int i = tid; i < NV4; i += STH) {
                    float4 v = xr[i];
                    rs_insert(pass, f2k(v.x), arena, rep, sel0, sel1, sel2, sel3);
                    rs_insert(pass, f2k(v.y), arena, rep, sel0, sel1, sel2, sel3);
                    rs_insert(pass, f2k(v.z), arena, rep, sel0, sel1, sel2, sel3);
                    rs_insert(pass, f2k(v.w), arena, rep, sel0, sel1, sel2, sel3);
                }
            }
            __syncthreads();

            if (pass == 1) {
                // fold replicas 1..7 into replica 0 (each thread owns distinct bins)
                for (int b = tid; b < SELBINS; b += STH) {
                    unsigned int s = arena[b];
                    #pragma unroll
                    for (int r = 1; r < REP; r++) s += arena[r * RSTR + b];
                    arena[b] = s;
                }
                __syncthreads();
            }

            // locate: warp q handles rank q
            if (wid < 4) {
                unsigned int* h = arena + ((pass == 1) ? 0 : wid * SELBINS);
                unsigned int lr = s_lr[wid];
                int base = lane * 64;
                unsigned int s = 0;
                #pragma unroll 8
                for (int i = 0; i < 64; i++) s += h[base + i];
                unsigned int inc2 = s;
                #pragma unroll
                for (int o = 1; o < 32; o <<= 1) {
                    unsigned int t = __shfl_up_sync(FULLM, inc2, o);
                    if (lane >= o) inc2 += t;
                }
                unsigned int run = inc2 - s;
                for (int i = 0; i < 64; i++) {
                    unsigned int cc = h[base + i];
                    if (run <= lr && lr < run + cc) {
                        unsigned int bin = (unsigned int)(base + i);
                        unsigned int ns = (pass == 1) ? bin
                                        : (pass == 2) ? ((s_sel[wid] << 11) | bin)
                                                      : ((s_sel[wid] << 10) | bin);
                        s_sel[wid] = ns;
                        s_lr[wid]  = lr - run;
                    }
                    run += cc;
                }
            }
            __syncthreads();
        }

        if (tid == 0) {
            int redo = 0;
            if (mode == 0) {
                // selected order stats must lie strictly beyond +/-2 for rank mapping to hold
                if (!(s_sel[1] < KNEG2 && s_sel[2] > KPOS2)) { redo = 1; s_mode = 1; }
            }
            s_redo = redo;
        }
        __syncthreads();
        if (!s_redo) break;
    }

    if (tid == 0) {
        float v[4];
        #pragma unroll
        for (int q = 0; q < 4; q++) v[q] = k2f(s_sel[q]);

        double posLo  = 0.01 * (double)(NPERROW - 1);
        double posHi  = 0.99 * (double)(NPERROW - 1);
        double fracLo = posLo - 2621.0;
        double fracHi = posHi - 259521.0;

        double i1  = (double)v[0] + fracLo * ((double)v[1] - (double)v[0]);
        double i99 = (double)v[2] + fracHi * ((double)v[3] - (double)v[2]);

        float alpha = alpha_p[0];
        float beta  = beta_p[0];
        float th = (float)(i1 + (i99 - i1) * (double)alpha);
        float mask   = (th > 1e-14f) ? 1.0f : 0.0f;
        float th_new = th * mask + (1.0f - mask);
        g_scale[row] = beta / th_new;
        g_t[row]     = th * mask;
    }
}

// ===================== Kernel 3: streaming gate =====================
__global__ __launch_bounds__(GTH)
void gate_kernel(const float* __restrict__ x, float* __restrict__ out)
{
    const int c   = blockIdx.x;
    const int row = c >> 4;            // CHUNKS = 16
    const int chk = c & 15;
    const float4* xr   = (const float4*)(x   + (size_t)row * NPERROW) + (size_t)chk * V4C;
    float4*       outr = (float4*)      (out + (size_t)row * NPERROW) + (size_t)chk * V4C;

    const float scale = g_scale[row];
    const float t     = g_t[row];
    const float L2E   = 1.4426950408889634f;
    const float a = scale * L2E;        // exp(-(scale*(|x|-t))) = 2^(-a*|x| + b)
    const float b = scale * t * L2E;

    #pragma unroll 4
    for (int i = threadIdx.x; i < V4C; i += GTH) {
        float4 v = __ldcs(&xr[i]);
        float4 o;
        o.x = fmaxf(v.x, 0.0f) * rcpa(1.0f + ex2a(fmaf(fabsf(v.x), -a, b)));
        o.y = fmaxf(v.y, 0.0f) * rcpa(1.0f + ex2a(fmaf(fabsf(v.y), -a, b)));
        o.z = fmaxf(v.z, 0.0f) * rcpa(1.0f + ex2a(fmaf(fabsf(v.z), -a, b)));
        o.w = fmaxf(v.w, 0.0f) * rcpa(1.0f + ex2a(fmaf(fabsf(v.w), -a, b)));
        __stcs(&outr[i], o);
    }
}

extern "C" void kernel_launch(void* const* d_in, const int* in_sizes, int n_in,
                              void* d_out, int out_size)
{
    const float* x     = (const float*)d_in[0];
    const float* alpha = (const float*)d_in[1];
    const float* beta  = (const float*)d_in[2];
    float* out = (float*)d_out;

    cudaFuncSetAttribute(select_kernel, cudaFuncAttributeMaxDynamicSharedMemorySize, SEL_SMEM_BYTES);

    gather_kernel<<<NROWS * CHUNKS, GTH>>>(x);
    select_kernel<<<NROWS, STH, SEL_SMEM_BYTES>>>(x, alpha, beta);
    gate_kernel<<<NROWS * CHUNKS, GTH>>>(x, out);
}

// round 11
// speedup vs baseline: 1.9693x; 1.1399x over previous
#include <cuda_runtime.h>
#include <math.h>

#define NPERROW (512*512)            // 262144
#define NROWS   128
#define NV4     (NPERROW/4)          // 65536
#define FULLM   0xFFFFFFFFu

// ---- gather / gate shape ----
#define CHUNKS  16
#define GTH     256
#define V4C     (NV4/CHUNKS)         // 4096 float4 per chunk
#define V4T     (V4C/GTH)            // 16 float4 per thread
#define GWARPS  (GTH/32)             // 8
#define TCAP    24                   // per-thread stage cap (exp 2.9, ~11 sigma)
#define CSEG    1024                 // per-chunk global segment cap (exp ~746)

// ---- selection (R7-proven 3-level histogram radix-select) ----
#define NTHREADS 1024
#define NBINS   16384                // top-14-bit histogram (key bits [18,32))
#define BPT     (NBINS/NTHREADS)     // 16
#define MCAP    (CHUNKS*CSEG)        // 16384
#define SMEM_WORDS (NBINS + MCAP + 4096 + 1024)   // 37888
#define SMEM_BYTES (SMEM_WORDS*4)                 // 151552

__device__ unsigned int g_buf[NROWS][CHUNKS*CSEG];   // 8 MB scratch
__device__ unsigned int g_ccnt[NROWS][CHUNKS];       // per-chunk counts (0xFFFFFFFF = overflow)
__device__ float g_scale[NROWS];
__device__ float g_t[NROWS];

// monotone float -> uint key
__device__ __forceinline__ unsigned int f2k(float f) {
    unsigned int u = __float_as_uint(f);
    return u ^ ((unsigned int)((int)u >> 31) | 0x80000000u);
}
__device__ __forceinline__ float k2f(unsigned int k) {
    unsigned int u = (k & 0x80000000u) ? (k ^ 0x80000000u) : ~k;
    return __uint_as_float(u);
}
__device__ __forceinline__ float ex2a(float x){ float r; asm("ex2.approx.ftz.f32 %0, %1;" : "=f"(r) : "f"(x)); return r; }
__device__ __forceinline__ float rcpa(float x){ float r; asm("rcp.approx.ftz.f32 %0, %1;" : "=f"(r) : "f"(x)); return r; }

// ===================== Kernel 1: wide tail gather (8-deep MLP batching) =====================
__global__ __launch_bounds__(GTH)
void gather_kernel(const float* __restrict__ x)
{
    __shared__ unsigned int stage[TCAP * GTH];   // per-thread stripes, conflict-free
    __shared__ unsigned int wsum[GWARPS];
    __shared__ int s_ov;

    const int tid  = threadIdx.x;
    const int lane = tid & 31;
    const int wid  = tid >> 5;
    const int row  = blockIdx.x >> 4;
    const int chk  = blockIdx.x & (CHUNKS - 1);
    const float4* xr = (const float4*)(x + (size_t)row * NPERROW) + (size_t)chk * V4C;

    if (tid == 0) s_ov = 0;
    __syncthreads();

    unsigned int cnt = 0;
    #pragma unroll
    for (int it = 0; it < V4T / 8; it++) {
        // batch 8 independent 128-bit loads: 128 B in flight per thread
        float4 v[8];
        #pragma unroll
        for (int s = 0; s < 8; s++)
            v[s] = __ldcs(&xr[tid + (it * 8 + s) * GTH]);

        #pragma unroll
        for (int s = 0; s < 8; s++) {
            if (fabsf(v[s].x) > 2.0f) { if (cnt < TCAP) stage[cnt * GTH + tid] = f2k(v[s].x); cnt++; }
            if (fabsf(v[s].y) > 2.0f) { if (cnt < TCAP) stage[cnt * GTH + tid] = f2k(v[s].y); cnt++; }
            if (fabsf(v[s].z) > 2.0f) { if (cnt < TCAP) stage[cnt * GTH + tid] = f2k(v[s].z); cnt++; }
            if (fabsf(v[s].w) > 2.0f) { if (cnt < TCAP) stage[cnt * GTH + tid] = f2k(v[s].w); cnt++; }
        }
    }
    if (cnt > TCAP) s_ov = 1;   // benign race; ordered by barriers below

    // block exclusive scan of per-thread counts
    unsigned int inc = cnt;
    #pragma unroll
    for (int o = 1; o < 32; o <<= 1) {
        unsigned int t = __shfl_up_sync(FULLM, inc, o);
        if (lane >= o) inc += t;
    }
    if (lane == 31) wsum[wid] = inc;
    __syncthreads();
    if (tid < GWARPS) {
        unsigned int w = wsum[tid];
        #pragma unroll
        for (int o = 1; o < GWARPS; o <<= 1) {
            unsigned int t = __shfl_up_sync(0xFFu, w, o);
            if (tid >= o) w += t;
        }
        wsum[tid] = w;
    }
    __syncthreads();

    unsigned int pre   = (wid ? wsum[wid - 1] : 0u) + inc - cnt;
    unsigned int total = wsum[GWARPS - 1];
    int ov = s_ov || (total > CSEG);

    if (!ov) {
        unsigned int* dst = &g_buf[row][chk * CSEG + pre];
        for (unsigned int j = 0; j < cnt; j++) dst[j] = stage[j * GTH + tid];
    }
    if (tid == 0) g_ccnt[row][chk] = ov ? 0xFFFFFFFFu : total;
}

// ===================== Kernel 2: per-row selection (R7-proven radix-select) =====================
extern __shared__ unsigned int smem_u[];

// block-wide: exclusive-scan bank h[0..n), locate slot s with pre <= lr < pre+h[s].
__device__ __forceinline__ void scan_locate(unsigned int* h, int n, unsigned int lr,
                                            int* slot, unsigned int* pre,
                                            unsigned int* wsum,
                                            int tid, int lane, int wid)
{
    unsigned int c = (tid < n) ? h[tid] : 0u;
    unsigned int inc = c;
    #pragma unroll
    for (int o = 1; o < 32; o <<= 1) {
        unsigned int t = __shfl_up_sync(FULLM, inc, o);
        if (lane >= o) inc += t;
    }
    if (lane == 31) wsum[wid] = inc;
    __syncthreads();
    if (tid < 32) {
        unsigned int w = wsum[tid];
        #pragma unroll
        for (int o = 1; o < 32; o <<= 1) {
            unsigned int t = __shfl_up_sync(FULLM, w, o);
            if (lane >= o) w += t;
        }
        wsum[tid] = w;
    }
    __syncthreads();
    unsigned int p = (wid ? wsum[wid - 1] : 0u) + inc - c;
    if (tid < n && lr >= p && lr < p + c) { *slot = tid; *pre = p; }
    __syncthreads();
}

__global__ __launch_bounds__(NTHREADS, 1)
void select_kernel(const float* __restrict__ x,
                   const float* __restrict__ alpha_p,
                   const float* __restrict__ beta_p)
{
    unsigned int* hist = smem_u;           // NBINS  (16384)
    unsigned int* mix  = hist + NBINS;     // MCAP   (16384)
    unsigned int* h2   = mix + MCAP;       // 4096 (4 banks x 1024)
    unsigned int* h3   = h2 + 4096;        // 1024 (4 banks x 256)

    __shared__ unsigned int wsum[32];
    __shared__ unsigned int cpre[CHUNKS + 1];
    __shared__ unsigned int s_M;
    __shared__ int          s_bad;
    __shared__ int          binOf[4];
    __shared__ unsigned int preOf[4];
    __shared__ int          slot2[4];
    __shared__ unsigned int pre2[4];
    __shared__ int          slot3[4];
    __shared__ unsigned int pre3[4];

    const int tid  = threadIdx.x;
    const int lane = tid & 31;
    const int wid  = tid >> 5;
    const int row  = blockIdx.x;
    const float4* xr = (const float4*)(x + (size_t)row * NPERROW);

    if (tid == 0) {
        unsigned int t = 0; int bad = 0;
        #pragma unroll
        for (int c = 0; c < CHUNKS; c++) {
            unsigned int cc = g_ccnt[row][c];
            if (cc > CSEG) { bad = 1; cc = 0; }
            cpre[c] = t;
            t += cc;
        }
        cpre[CHUNKS] = t;
        if (t < 5246u) bad = 1;   // both tails need >= 2623 elements
        s_M = t; s_bad = bad;
    }
    __syncthreads();

    const unsigned int M = s_M;
    int mode = s_bad ? 1 : 0;   // 0 = gathered tail set, 1 = exact full-row fallback

    if (mode == 0) {
        #pragma unroll
        for (int c = 0; c < CHUNKS; c++) {
            unsigned int cnt = cpre[c + 1] - cpre[c];   // <= CSEG = NTHREADS
            if ((unsigned int)tid < cnt) mix[cpre[c] + tid] = g_buf[row][c * CSEG + tid];
        }
    }
    __syncthreads();

    const unsigned int BL2 = f2k(-2.0f) >> 18;
    const unsigned int BH2 = f2k( 2.0f) >> 18;
    unsigned int R[4];

    // ---------------- L1: 14-bit histogram + inline locate ----------------
    for (;;) {
        if (mode == 0) { R[0] = 2621u; R[1] = 2622u; R[2] = M - 2623u; R[3] = M - 2622u; }
        else           { R[0] = 2621u; R[1] = 2622u; R[2] = 259521u;   R[3] = 259522u;  }

        #pragma unroll
        for (int j = 0; j < BPT; j++) hist[tid + j * NTHREADS] = 0u;
        __syncthreads();

        if (mode == 0) {
            for (unsigned int i = tid; i < M; i += NTHREADS)
                atomicAdd(&hist[mix[i] >> 18], 1u);
        } else {
            for (int i = tid; i < NV4; i += NTHREADS) {
                float4 v = xr[i];
                atomicAdd(&hist[f2k(v.x) >> 18], 1u);
                atomicAdd(&hist[f2k(v.y) >> 18], 1u);
                atomicAdd(&hist[f2k(v.z) >> 18], 1u);
                atomicAdd(&hist[f2k(v.w) >> 18], 1u);
            }
        }
        __syncthreads();

        // shfl-based scan over 16384 bins + inline rank locate
        unsigned int loc[BPT];
        unsigned int s = 0;
        #pragma unroll
        for (int j = 0; j < BPT; j++) { loc[j] = hist[tid * BPT + j]; s += loc[j]; }
        unsigned int inc = s;
        #pragma unroll
        for (int o = 1; o < 32; o <<= 1) {
            unsigned int t = __shfl_up_sync(FULLM, inc, o);
            if (lane >= o) inc += t;
        }
        if (lane == 31) wsum[wid] = inc;
        __syncthreads();
        if (tid < 32) {
            unsigned int w = wsum[tid];
            #pragma unroll
            for (int o = 1; o < 32; o <<= 1) {
                unsigned int t = __shfl_up_sync(FULLM, w, o);
                if (lane >= o) w += t;
            }
            wsum[tid] = w;
        }
        __syncthreads();
        unsigned int run = (wid ? wsum[wid - 1] : 0u) + inc - s;
        #pragma unroll
        for (int j = 0; j < BPT; j++) {
            unsigned int c = loc[j];
            int b = tid * BPT + j;
            #pragma unroll
            for (int q = 0; q < 4; q++)
                if (run <= R[q] && R[q] < run + c) { binOf[q] = b; preOf[q] = run; }
            run += c;
        }
        __syncthreads();

        if (mode == 0) {
            if (binOf[1] > (int)BL2 || binOf[2] < (int)BH2) { mode = 1; __syncthreads(); continue; }
        }
        break;
    }

    // ---------------- L2: 4 banks x 1024 sub-bins (key bits [8,18)) ----------------
    for (int j = tid; j < 4096; j += NTHREADS) h2[j] = 0u;
    __syncthreads();
    if (mode == 0) {
        for (unsigned int i = tid; i < M; i += NTHREADS) {
            unsigned int k = mix[i];
            int b = (int)(k >> 18);
            unsigned int sub = (k >> 8) & 1023u;
            #pragma unroll
            for (int q = 0; q < 4; q++)
                if (b == binOf[q]) atomicAdd(&h2[q * 1024 + sub], 1u);
        }
    } else {
        for (int i = tid; i < NV4; i += NTHREADS) {
            float4 v = xr[i];
            unsigned int ks[4] = {f2k(v.x), f2k(v.y), f2k(v.z), f2k(v.w)};
            #pragma unroll
            for (int e = 0; e < 4; e++) {
                unsigned int k = ks[e];
                int b = (int)(k >> 18);
                unsigned int sub = (k >> 8) & 1023u;
                #pragma unroll
                for (int q = 0; q < 4; q++)
                    if (b == binOf[q]) atomicAdd(&h2[q * 1024 + sub], 1u);
            }
        }
    }
    __syncthreads();
    #pragma unroll
    for (int q = 0; q < 4; q++)
        scan_locate(h2 + q * 1024, 1024, R[q] - preOf[q], &slot2[q], &pre2[q], wsum, tid, lane, wid);

    // ---------------- L3: 4 banks x 256 (key bits [0,8)) -> exact key ----------------
    unsigned int tgt24[4];
    #pragma unroll
    for (int q = 0; q < 4; q++) tgt24[q] = ((unsigned int)binOf[q] << 10) | (unsigned int)slot2[q];

    for (int j = tid; j < 1024; j += NTHREADS) h3[j] = 0u;
    __syncthreads();
    if (mode == 0) {
        for (unsigned int i = tid; i < M; i += NTHREADS) {
            unsigned int k = mix[i];
            unsigned int p24 = k >> 8;
            #pragma unroll
            for (int q = 0; q < 4; q++)
                if (p24 == tgt24[q]) atomicAdd(&h3[q * 256 + (k & 255u)], 1u);
        }
    } else {
        for (int i = tid; i < NV4; i += NTHREADS) {
            float4 v = xr[i];
            unsigned int ks[4] = {f2k(v.x), f2k(v.y), f2k(v.z), f2k(v.w)};
            #pragma unroll
            for (int e = 0; e < 4; e++) {
                unsigned int k = ks[e];
                unsigned int p24 = k >> 8;
                #pragma unroll
                for (int q = 0; q < 4; q++)
                    if (p24 == tgt24[q]) atomicAdd(&h3[q * 256 + (k & 255u)], 1u);
            }
        }
    }
    __syncthreads();
    #pragma unroll
    for (int q = 0; q < 4; q++)
        scan_locate(h3 + q * 256, 256, R[q] - preOf[q] - pre2[q], &slot3[q], &pre3[q], wsum, tid, lane, wid);

    // ---------------- threshold ----------------
    if (tid == 0) {
        float v[4];
        #pragma unroll
        for (int q = 0; q < 4; q++)
            v[q] = k2f((tgt24[q] << 8) | (unsigned int)slot3[q]);

        double posLo  = 0.01 * (double)(NPERROW - 1);
        double posHi  = 0.99 * (double)(NPERROW - 1);
        double fracLo = posLo - 2621.0;
        double fracHi = posHi - 259521.0;

        double i1  = (double)v[0] + fracLo * ((double)v[1] - (double)v[0]);
        double i99 = (double)v[2] + fracHi * ((double)v[3] - (double)v[2]);

        float alpha = alpha_p[0];
        float beta  = beta_p[0];
        float th = (float)(i1 + (i99 - i1) * (double)alpha);
        float mask   = (th > 1e-14f) ? 1.0f : 0.0f;
        float th_new = th * mask + (1.0f - mask);
        g_scale[row] = beta / th_new;
        g_t[row]     = th * mask;
    }
}

// ===================== Kernel 3: streaming gate =====================
__global__ __launch_bounds__(GTH)
void gate_kernel(const float* __restrict__ x, float* __restrict__ out)
{
    const int c   = blockIdx.x;
    const int row = c >> 4;            // CHUNKS = 16
    const int chk = c & 15;
    const float4* xr   = (const float4*)(x   + (size_t)row * NPERROW) + (size_t)chk * V4C;
    float4*       outr = (float4*)      (out + (size_t)row * NPERROW) + (size_t)chk * V4C;

    const float scale = g_scale[row];
    const float t     = g_t[row];
    const float L2E   = 1.4426950408889634f;
    const float a = scale * L2E;        // exp(-(scale*(|x|-t))) = 2^(-a*|x| + b)
    const float b = scale * t * L2E;

    #pragma unroll 4
    for (int i = threadIdx.x; i < V4C; i += GTH) {
        float4 v = __ldcs(&xr[i]);
        float4 o;
        o.x = fmaxf(v.x, 0.0f) * rcpa(1.0f + ex2a(fmaf(fabsf(v.x), -a, b)));
        o.y = fmaxf(v.y, 0.0f) * rcpa(1.0f + ex2a(fmaf(fabsf(v.y), -a, b)));
        o.z = fmaxf(v.z, 0.0f) * rcpa(1.0f + ex2a(fmaf(fabsf(v.z), -a, b)));
        o.w = fmaxf(v.w, 0.0f) * rcpa(1.0f + ex2a(fmaf(fabsf(v.w), -a, b)));
        __stcs(&outr[i], o);
    }
}

extern "C" void kernel_launch(void* const* d_in, const int* in_sizes, int n_in,
                              void* d_out, int out_size)
{
    const float* x     = (const float*)d_in[0];
    const float* alpha = (const float*)d_in[1];
    const float* beta  = (const float*)d_in[2];
    float* out = (float*)d_out;

    cudaFuncSetAttribute(select_kernel, cudaFuncAttributeMaxDynamicSharedMemorySize, SMEM_BYTES);

    gather_kernel<<<NROWS * CHUNKS, GTH>>>(x);
    select_kernel<<<NROWS, NTHREADS, SMEM_BYTES>>>(x, alpha, beta);
    gate_kernel<<<NROWS * CHUNKS, GTH>>>(x, out);
}